// round 7
// baseline (speedup 1.0000x reference)
#include <cuda_runtime.h>
#include <cstdint>

typedef unsigned long long ull;

#define NSPECIES 4
#define FDIM 128
#define HDIM 64
#define MAXN 2000000
#define TM 128
#define LDF 132

// ---------------- device scratch ----------------
__device__ int g_meta[8];     // [0..3] counts, [4..7] scatter cursors
__device__ int g_sorted[MAXN];

// ---------------- per-stage constant weights (one species) ----------------
__constant__ float c_W1[FDIM * HDIM];   // [k][j]
__constant__ float c_W2[HDIM * HDIM];   // [k][j]
__constant__ float c_b1[HDIM];
__constant__ float c_b2[HDIM];
__constant__ float c_W3[HDIM];
__constant__ float c_b3[1];

// ---------------- packed f32x2 helpers (validated) ----------------
__device__ __forceinline__ ull pk(float lo, float hi) {
    ull r;
    asm("mov.b64 %0, {%1, %2};" : "=l"(r)
        : "r"(__float_as_uint(lo)), "r"(__float_as_uint(hi)));
    return r;
}
__device__ __forceinline__ void upk(ull v, float& lo, float& hi) {
    unsigned a, b;
    asm("mov.b64 {%0, %1}, %2;" : "=r"(a), "=r"(b) : "l"(v));
    lo = __uint_as_float(a);
    hi = __uint_as_float(b);
}
__device__ __forceinline__ ull ffma2(ull a, ull b, ull c) {
    ull d;
    asm("fma.rn.f32x2 %0, %1, %2, %3;" : "=l"(d) : "l"(a), "l"(b), "l"(c));
    return d;
}
__device__ __forceinline__ float fast_tanh(float x) {
    // tanh(x) = 1 - 2/(exp(2x)+1); stable at +/-inf.
    float e = __expf(2.0f * x);
    return 1.0f - __fdividef(2.0f, e + 1.0f);
}

// ---------------- species dtype detect + counting sort (validated) -------
__device__ __forceinline__ int detect64(const void* sp, int n) {
    const long long* p = (const long long*)sp;
    int m = n / 2 < 128 ? n / 2 : 128;
    int ok = 1;
    #pragma unroll 1
    for (int i = 0; i < m; i++) { long long v = p[i]; if (v < 0 || v > 3) { ok = 0; break; } }
    return ok;
}
__device__ __forceinline__ int load_sp(const void* sp, int i, int is64) {
    return is64 ? (int)((const long long*)sp)[i] : ((const int*)sp)[i];
}
__global__ void hist_kernel(const void* __restrict__ sp, int n) {
    __shared__ int hs[NSPECIES];
    if (threadIdx.x < NSPECIES) hs[threadIdx.x] = 0;
    __syncthreads();
    const int is64 = detect64(sp, n);
    const int stride = gridDim.x * blockDim.x;
    for (int i = blockIdx.x * blockDim.x + threadIdx.x; i < n; i += stride)
        atomicAdd(&hs[load_sp(sp, i, is64)], 1);
    __syncthreads();
    if (threadIdx.x < NSPECIES) atomicAdd(&g_meta[threadIdx.x], hs[threadIdx.x]);
}
__global__ void scatter_kernel(const void* __restrict__ sp, int n) {
    const int is64 = detect64(sp, n);
    int offs[NSPECIES];
    { int a = 0;
      #pragma unroll
      for (int s = 0; s < NSPECIES; s++) { offs[s] = a; a += g_meta[s]; } }
    const int stride = gridDim.x * blockDim.x;
    const int lane = threadIdx.x & 31;
    for (int i = blockIdx.x * blockDim.x + threadIdx.x; i < n; i += stride) {
        int s = load_sp(sp, i, is64);
        unsigned act = __activemask();
        unsigned peers = __match_any_sync(act, s);
        int leader = __ffs(peers) - 1;
        int cnt = __popc(peers);
        int base = 0;
        if (lane == leader) base = atomicAdd(&g_meta[NSPECIES + s], cnt);
        base = __shfl_sync(peers, base, leader);
        g_sorted[offs[s] + base + __popc(peers & ((1u << lane) - 1u))] = i;
    }
}

// ---------------- SMEM layout (floats): two Ft tiles + partials ----------
#define OFF_FT0 0
#define OFF_FT1 (OFF_FT0 + FDIM * LDF)       // 16896
#define OFF_EP  (OFF_FT1 + FDIM * LDF)       // 33792 : Epart[2][8][128]
#define SMEM_FLOATS (OFF_EP + 2 * 8 * TM)    // 35840 floats = 143360 B

extern __shared__ float sm[];

#define GBAR(id) asm volatile("bar.sync %0, 128;" :: "r"(id) : "memory")

// One species per launch; weights in the constant bank.
__global__ void __launch_bounds__(256, 1)
mlp_stage_kernel(const float* __restrict__ feats,
                 float* __restrict__ out, int s_stage)
{
    const int tid = threadIdx.x;
    const int g   = tid >> 7;          // group 0/1 (independent tiles)
    const int gid = tid & 127;
    const int tx  = gid & 15;          // 16 atom-chunks
    const int ty  = gid >> 4;          // 8 hidden-groups of 8
    const int mA  = tx * 4;            // atoms mA..mA+3 and 64+mA..64+mA+3
    const int n0  = ty * 8;
    const int FT  = g ? OFF_FT1 : OFF_FT0;
    const int EP  = OFF_EP + g * 8 * TM;
    const int barid = 1 + g;

    // species range
    int beg = 0;
    #pragma unroll
    for (int s = 0; s < NSPECIES; s++) if (s < s_stage) beg += g_meta[s];
    const int cnt = g_meta[s_stage];
    const int ntiles = (cnt + TM - 1) / TM;

    // contiguous tile range per (CTA, group)
    const int nslots = gridDim.x * 2;
    const int slot = blockIdx.x * 2 + g;
    const int tpc = (ntiles + nslots - 1) / nslots;
    const int t0 = slot * tpc;
    const int t1 = min(t0 + tpc, ntiles);

    for (int t = t0; t < t1; t++) {
        const int start = beg + t * TM;
        const int m = min(TM, cnt - t * TM);

        // ---- gather feature tile, transposed Ft[k][row] ----
        {
            const int ridx = gid < m ? gid : m - 1;
            const int atom = g_sorted[start + ridx];
            const float4* src = (const float4*)(feats + (size_t)atom * FDIM);
            #pragma unroll 8
            for (int q = 0; q < 32; q++) {
                float4 v = src[q];
                const int k = q * 4;
                sm[FT + (k + 0) * LDF + gid] = v.x;
                sm[FT + (k + 1) * LDF + gid] = v.y;
                sm[FT + (k + 2) * LDF + gid] = v.z;
                sm[FT + (k + 3) * LDF + gid] = v.w;
            }
        }
        GBAR(barid);

        // ---- layer 1: acc[8 atoms][4 hidden-pairs]; W from constant ----
        ull acc[8][4];
        {
            const ull* b1p = (const ull*)(c_b1 + n0);
            const ull bi[4] = { b1p[0], b1p[1], b1p[2], b1p[3] };
            #pragma unroll
            for (int a = 0; a < 8; a++)
                #pragma unroll
                for (int np = 0; np < 4; np++) acc[a][np] = bi[np];

            #pragma unroll 4
            for (int k = 0; k < FDIM; k++) {
                const float4 a0 = *(const float4*)(sm + FT + k * LDF + mA);
                const float4 a1 = *(const float4*)(sm + FT + k * LDF + 64 + mA);
                const ulonglong2 w01 = *(const ulonglong2*)(c_W1 + k * HDIM + n0);
                const ulonglong2 w23 = *(const ulonglong2*)(c_W1 + k * HDIM + n0 + 4);
                const ull f[8] = { pk(a0.x, a0.x), pk(a0.y, a0.y), pk(a0.z, a0.z), pk(a0.w, a0.w),
                                   pk(a1.x, a1.x), pk(a1.y, a1.y), pk(a1.z, a1.z), pk(a1.w, a1.w) };
                const ull w[4] = { w01.x, w01.y, w23.x, w23.y };
                #pragma unroll
                for (int a = 0; a < 8; a++)
                    #pragma unroll
                    for (int np = 0; np < 4; np++)
                        acc[a][np] = ffma2(f[a], w[np], acc[a][np]);
            }
        }
        GBAR(barid);                    // Ft reads done before Ht overlay

        // ---- tanh -> Ht[j][atom] (overlays Ft rows 0..63) ----
        #pragma unroll
        for (int np = 0; np < 4; np++) {
            float lo[8], hi[8];
            #pragma unroll
            for (int a = 0; a < 8; a++) {
                float x, y;
                upk(acc[a][np], x, y);
                lo[a] = fast_tanh(x);
                hi[a] = fast_tanh(y);
            }
            *(float4*)(sm + FT + (n0 + 2 * np) * LDF + mA)          = make_float4(lo[0], lo[1], lo[2], lo[3]);
            *(float4*)(sm + FT + (n0 + 2 * np) * LDF + 64 + mA)     = make_float4(lo[4], lo[5], lo[6], lo[7]);
            *(float4*)(sm + FT + (n0 + 2 * np + 1) * LDF + mA)      = make_float4(hi[0], hi[1], hi[2], hi[3]);
            *(float4*)(sm + FT + (n0 + 2 * np + 1) * LDF + 64 + mA) = make_float4(hi[4], hi[5], hi[6], hi[7]);
        }
        GBAR(barid);

        // ---- layer 2 ----
        {
            const ull* b2p = (const ull*)(c_b2 + n0);
            const ull bi[4] = { b2p[0], b2p[1], b2p[2], b2p[3] };
            #pragma unroll
            for (int a = 0; a < 8; a++)
                #pragma unroll
                for (int np = 0; np < 4; np++) acc[a][np] = bi[np];

            #pragma unroll 4
            for (int k = 0; k < HDIM; k++) {
                const float4 a0 = *(const float4*)(sm + FT + k * LDF + mA);
                const float4 a1 = *(const float4*)(sm + FT + k * LDF + 64 + mA);
                const ulonglong2 w01 = *(const ulonglong2*)(c_W2 + k * HDIM + n0);
                const ulonglong2 w23 = *(const ulonglong2*)(c_W2 + k * HDIM + n0 + 4);
                const ull f[8] = { pk(a0.x, a0.x), pk(a0.y, a0.y), pk(a0.z, a0.z), pk(a0.w, a0.w),
                                   pk(a1.x, a1.x), pk(a1.y, a1.y), pk(a1.z, a1.z), pk(a1.w, a1.w) };
                const ull w[4] = { w01.x, w01.y, w23.x, w23.y };
                #pragma unroll
                for (int a = 0; a < 8; a++)
                    #pragma unroll
                    for (int np = 0; np < 4; np++)
                        acc[a][np] = ffma2(f[a], w[np], acc[a][np]);
            }
        }

        // ---- tanh, dot W3 slice, partial energies ----
        {
            const ull* w3p = (const ull*)(c_W3 + n0);
            const ull w3r[4] = { w3p[0], w3p[1], w3p[2], w3p[3] };
            #pragma unroll
            for (int a = 0; a < 8; a++) {
                ull e2 = pk(0.0f, 0.0f);
                #pragma unroll
                for (int np = 0; np < 4; np++) {
                    float x, y;
                    upk(acc[a][np], x, y);
                    e2 = ffma2(pk(fast_tanh(x), fast_tanh(y)), w3r[np], e2);
                }
                float e0, e1;
                upk(e2, e0, e1);
                const int col = (a < 4) ? (mA + a) : (64 + mA + a - 4);
                sm[EP + ty * TM + col] = e0 + e1;
            }
        }
        GBAR(barid);

        // ---- reduce 8 partials per atom ----
        if (gid < m) {
            float e = c_b3[0];
            #pragma unroll
            for (int q = 0; q < 8; q++) e += sm[EP + q * TM + gid];
            out[g_sorted[start + gid]] = e;
        }
        // next gather overwrites Ft only after this group's threads pass GBAR
    }
}

// ---------------- launch ----------------
extern "C" void kernel_launch(void* const* d_in, const int* in_sizes, int n_in,
                              void* d_out, int out_size)
{
    const float* feats   = (const float*)d_in[0];
    const void*  species = d_in[1];
    const float* W1 = (const float*)d_in[2];
    const float* b1 = (const float*)d_in[3];
    const float* W2 = (const float*)d_in[4];
    const float* b2 = (const float*)d_in[5];
    const float* W3 = (const float*)d_in[6];
    const float* b3 = (const float*)d_in[7];
    float* out = (float*)d_out;
    const int n = out_size;

    int dev = 0;
    cudaGetDevice(&dev);
    int nsm = 148;
    cudaDeviceGetAttribute(&nsm, cudaDevAttrMultiProcessorCount, dev);

    void* meta_addr = nullptr;
    cudaGetSymbolAddress(&meta_addr, g_meta);
    cudaMemsetAsync(meta_addr, 0, 8 * sizeof(int));

    hist_kernel<<<nsm, 256>>>(species, n);
    scatter_kernel<<<nsm, 256>>>(species, n);

    const size_t smem_bytes = SMEM_FLOATS * sizeof(float);
    cudaFuncSetAttribute(mlp_stage_kernel,
                         cudaFuncAttributeMaxDynamicSharedMemorySize,
                         (int)smem_bytes);

    for (int s = 0; s < NSPECIES; s++) {
        cudaMemcpyToSymbolAsync(c_W1, W1 + (size_t)s * FDIM * HDIM,
                                FDIM * HDIM * sizeof(float), 0, cudaMemcpyDeviceToDevice);
        cudaMemcpyToSymbolAsync(c_W2, W2 + (size_t)s * HDIM * HDIM,
                                HDIM * HDIM * sizeof(float), 0, cudaMemcpyDeviceToDevice);
        cudaMemcpyToSymbolAsync(c_b1, b1 + (size_t)s * HDIM,
                                HDIM * sizeof(float), 0, cudaMemcpyDeviceToDevice);
        cudaMemcpyToSymbolAsync(c_b2, b2 + (size_t)s * HDIM,
                                HDIM * sizeof(float), 0, cudaMemcpyDeviceToDevice);
        cudaMemcpyToSymbolAsync(c_W3, W3 + (size_t)s * HDIM,
                                HDIM * sizeof(float), 0, cudaMemcpyDeviceToDevice);
        cudaMemcpyToSymbolAsync(c_b3, b3 + (size_t)s,
                                sizeof(float), 0, cudaMemcpyDeviceToDevice);
        mlp_stage_kernel<<<nsm, 256, smem_bytes>>>(feats, out, s);
    }
}

// round 8
// speedup vs baseline: 1.1798x; 1.1798x over previous
#include <cuda_runtime.h>
#include <cstdint>

typedef unsigned long long ull;

#define NSPECIES 4
#define FDIM 128
#define HDIM 64
#define MAXN 2000000
#define TM 128
#define LDF 132

// ---------------- device scratch ----------------
__device__ int g_meta[8];     // [0..3] counts, [4..7] scatter cursors
__device__ int g_sorted[MAXN];

// ---------------- packed f32x2 helpers (validated) ----------------
__device__ __forceinline__ ull pk(float lo, float hi) {
    ull r;
    asm("mov.b64 %0, {%1, %2};" : "=l"(r)
        : "r"(__float_as_uint(lo)), "r"(__float_as_uint(hi)));
    return r;
}
__device__ __forceinline__ void upk(ull v, float& lo, float& hi) {
    unsigned a, b;
    asm("mov.b64 {%0, %1}, %2;" : "=r"(a), "=r"(b) : "l"(v));
    lo = __uint_as_float(a);
    hi = __uint_as_float(b);
}
__device__ __forceinline__ ull ffma2(ull a, ull b, ull c) {
    ull d;
    asm("fma.rn.f32x2 %0, %1, %2, %3;" : "=l"(d) : "l"(a), "l"(b), "l"(c));
    return d;
}
__device__ __forceinline__ float fast_tanh(float x) {
    // tanh(x) = 1 - 2/(exp(2x)+1); stable at +/-inf.
    float e = __expf(2.0f * x);
    return 1.0f - __fdividef(2.0f, e + 1.0f);
}
// uniform 16-byte weight fetch through L1 (read-only path)
__device__ __forceinline__ ulonglong2 ldg2(const float* p) {
    const ulonglong2* q = (const ulonglong2*)p;
    return __ldg(q);
}

// ---------------- species dtype detect + counting sort (validated) -------
__device__ __forceinline__ int detect64(const void* sp, int n) {
    const long long* p = (const long long*)sp;
    int m = n / 2 < 128 ? n / 2 : 128;
    int ok = 1;
    #pragma unroll 1
    for (int i = 0; i < m; i++) { long long v = p[i]; if (v < 0 || v > 3) { ok = 0; break; } }
    return ok;
}
__device__ __forceinline__ int load_sp(const void* sp, int i, int is64) {
    return is64 ? (int)((const long long*)sp)[i] : ((const int*)sp)[i];
}
__global__ void hist_kernel(const void* __restrict__ sp, int n) {
    __shared__ int hs[NSPECIES];
    if (threadIdx.x < NSPECIES) hs[threadIdx.x] = 0;
    __syncthreads();
    const int is64 = detect64(sp, n);
    const int stride = gridDim.x * blockDim.x;
    for (int i = blockIdx.x * blockDim.x + threadIdx.x; i < n; i += stride)
        atomicAdd(&hs[load_sp(sp, i, is64)], 1);
    __syncthreads();
    if (threadIdx.x < NSPECIES) atomicAdd(&g_meta[threadIdx.x], hs[threadIdx.x]);
}
__global__ void scatter_kernel(const void* __restrict__ sp, int n) {
    const int is64 = detect64(sp, n);
    int offs[NSPECIES];
    { int a = 0;
      #pragma unroll
      for (int s = 0; s < NSPECIES; s++) { offs[s] = a; a += g_meta[s]; } }
    const int stride = gridDim.x * blockDim.x;
    const int lane = threadIdx.x & 31;
    for (int i = blockIdx.x * blockDim.x + threadIdx.x; i < n; i += stride) {
        int s = load_sp(sp, i, is64);
        unsigned act = __activemask();
        unsigned peers = __match_any_sync(act, s);
        int leader = __ffs(peers) - 1;
        int cnt = __popc(peers);
        int base = 0;
        if (lane == leader) base = atomicAdd(&g_meta[NSPECIES + s], cnt);
        base = __shfl_sync(peers, base, leader);
        g_sorted[offs[s] + base + __popc(peers & ((1u << lane) - 1u))] = i;
    }
}

// ---------------- SMEM layout (floats): two Ft tiles + partials ----------
#define OFF_FT0 0
#define OFF_FT1 (OFF_FT0 + FDIM * LDF)       // 16896
#define OFF_EP  (OFF_FT1 + FDIM * LDF)       // 33792 : Epart[2][8][128]
#define SMEM_FLOATS (OFF_EP + 2 * 8 * TM)    // 35840 floats = 143360 B

extern __shared__ float sm[];

#define GBAR(id) asm volatile("bar.sync %0, 128;" :: "r"(id) : "memory")

__global__ void __launch_bounds__(256, 1)
mlp_ldg_kernel(const float* __restrict__ feats,
               const float* __restrict__ W1, const float* __restrict__ b1,
               const float* __restrict__ W2, const float* __restrict__ b2,
               const float* __restrict__ W3, const float* __restrict__ b3,
               float* __restrict__ out)
{
    const int tid = threadIdx.x;
    const int g   = tid >> 7;          // group 0/1 (independent tiles)
    const int gid = tid & 127;
    const int tx  = gid & 15;
    const int ty  = gid >> 4;
    const int mA  = tx * 4;            // atoms mA..mA+3 and 64+mA..64+mA+3
    const int n0  = ty * 8;
    const int FT  = g ? OFF_FT1 : OFF_FT0;
    const int EP  = OFF_EP + g * 8 * TM;
    const int barid = 1 + g;

    // ---- species / tile tables ----
    int beg[NSPECIES], cnt[NSPECIES], tp[NSPECIES + 1];
    { int a = 0, t = 0;
      #pragma unroll
      for (int s = 0; s < NSPECIES; s++) {
          cnt[s] = g_meta[s];
          beg[s] = a; a += cnt[s];
          tp[s] = t; t += (cnt[s] + TM - 1) / TM;
      }
      tp[NSPECIES] = t; }
    const int ntiles = tp[NSPECIES];

    // contiguous tile range per (CTA, group) slot
    const int nslots = gridDim.x * 2;
    const int slot = blockIdx.x * 2 + g;
    const int tpc = (ntiles + nslots - 1) / nslots;
    const int t0 = slot * tpc;
    const int t1 = min(t0 + tpc, ntiles);

    for (int t = t0; t < t1; t++) {
        int s = 3;
        if (t < tp[1]) s = 0; else if (t < tp[2]) s = 1; else if (t < tp[3]) s = 2;
        const int start = beg[s] + (t - tp[s]) * TM;
        const int m = min(TM, beg[s] + cnt[s] - start);

        const float* W1s = W1 + (size_t)s * FDIM * HDIM;
        const float* W2s = W2 + (size_t)s * HDIM * HDIM;

        // ---- gather feature tile, transposed Ft[k][row] ----
        {
            const int ridx = gid < m ? gid : m - 1;
            const int atom = g_sorted[start + ridx];
            const float4* src = (const float4*)(feats + (size_t)atom * FDIM);
            #pragma unroll 8
            for (int q = 0; q < 32; q++) {
                float4 v = src[q];
                const int k = q * 4;
                sm[FT + (k + 0) * LDF + gid] = v.x;
                sm[FT + (k + 1) * LDF + gid] = v.y;
                sm[FT + (k + 2) * LDF + gid] = v.z;
                sm[FT + (k + 3) * LDF + gid] = v.w;
            }
        }
        GBAR(barid);

        // ---- layer 1: acc[8 atoms][4 hidden-pairs]; W uniform via LDG/L1 ----
        ull acc[8][4];
        {
            const ull* b1p = (const ull*)(b1 + s * HDIM + n0);
            const ull bi[4] = { __ldg(b1p), __ldg(b1p + 1), __ldg(b1p + 2), __ldg(b1p + 3) };
            #pragma unroll
            for (int a = 0; a < 8; a++)
                #pragma unroll
                for (int np = 0; np < 4; np++) acc[a][np] = bi[np];

            #pragma unroll 4
            for (int k = 0; k < FDIM; k++) {
                const float4 a0 = *(const float4*)(sm + FT + k * LDF + mA);
                const float4 a1 = *(const float4*)(sm + FT + k * LDF + 64 + mA);
                const ulonglong2 w01 = ldg2(W1s + k * HDIM + n0);
                const ulonglong2 w23 = ldg2(W1s + k * HDIM + n0 + 4);
                const ull f[8] = { pk(a0.x, a0.x), pk(a0.y, a0.y), pk(a0.z, a0.z), pk(a0.w, a0.w),
                                   pk(a1.x, a1.x), pk(a1.y, a1.y), pk(a1.z, a1.z), pk(a1.w, a1.w) };
                const ull w[4] = { w01.x, w01.y, w23.x, w23.y };
                #pragma unroll
                for (int a = 0; a < 8; a++)
                    #pragma unroll
                    for (int np = 0; np < 4; np++)
                        acc[a][np] = ffma2(f[a], w[np], acc[a][np]);
            }
        }
        GBAR(barid);                    // Ft reads done before Ht overlay

        // ---- tanh -> Ht[j][atom] (overlays Ft rows 0..63) ----
        #pragma unroll
        for (int np = 0; np < 4; np++) {
            float lo[8], hi[8];
            #pragma unroll
            for (int a = 0; a < 8; a++) {
                float x, y;
                upk(acc[a][np], x, y);
                lo[a] = fast_tanh(x);
                hi[a] = fast_tanh(y);
            }
            *(float4*)(sm + FT + (n0 + 2 * np) * LDF + mA)          = make_float4(lo[0], lo[1], lo[2], lo[3]);
            *(float4*)(sm + FT + (n0 + 2 * np) * LDF + 64 + mA)     = make_float4(lo[4], lo[5], lo[6], lo[7]);
            *(float4*)(sm + FT + (n0 + 2 * np + 1) * LDF + mA)      = make_float4(hi[0], hi[1], hi[2], hi[3]);
            *(float4*)(sm + FT + (n0 + 2 * np + 1) * LDF + 64 + mA) = make_float4(hi[4], hi[5], hi[6], hi[7]);
        }
        GBAR(barid);

        // ---- layer 2 ----
        {
            const ull* b2p = (const ull*)(b2 + s * HDIM + n0);
            const ull bi[4] = { __ldg(b2p), __ldg(b2p + 1), __ldg(b2p + 2), __ldg(b2p + 3) };
            #pragma unroll
            for (int a = 0; a < 8; a++)
                #pragma unroll
                for (int np = 0; np < 4; np++) acc[a][np] = bi[np];

            #pragma unroll 4
            for (int k = 0; k < HDIM; k++) {
                const float4 a0 = *(const float4*)(sm + FT + k * LDF + mA);
                const float4 a1 = *(const float4*)(sm + FT + k * LDF + 64 + mA);
                const ulonglong2 w01 = ldg2(W2s + k * HDIM + n0);
                const ulonglong2 w23 = ldg2(W2s + k * HDIM + n0 + 4);
                const ull f[8] = { pk(a0.x, a0.x), pk(a0.y, a0.y), pk(a0.z, a0.z), pk(a0.w, a0.w),
                                   pk(a1.x, a1.x), pk(a1.y, a1.y), pk(a1.z, a1.z), pk(a1.w, a1.w) };
                const ull w[4] = { w01.x, w01.y, w23.x, w23.y };
                #pragma unroll
                for (int a = 0; a < 8; a++)
                    #pragma unroll
                    for (int np = 0; np < 4; np++)
                        acc[a][np] = ffma2(f[a], w[np], acc[a][np]);
            }
        }

        // ---- tanh, dot W3 slice, partial energies ----
        {
            const ull* w3p = (const ull*)(W3 + s * HDIM + n0);
            const ull w3r[4] = { __ldg(w3p), __ldg(w3p + 1), __ldg(w3p + 2), __ldg(w3p + 3) };
            #pragma unroll
            for (int a = 0; a < 8; a++) {
                ull e2 = pk(0.0f, 0.0f);
                #pragma unroll
                for (int np = 0; np < 4; np++) {
                    float x, y;
                    upk(acc[a][np], x, y);
                    e2 = ffma2(pk(fast_tanh(x), fast_tanh(y)), w3r[np], e2);
                }
                float e0, e1;
                upk(e2, e0, e1);
                const int col = (a < 4) ? (mA + a) : (64 + mA + a - 4);
                sm[EP + ty * TM + col] = e0 + e1;
            }
        }
        GBAR(barid);

        // ---- reduce 8 partials per atom ----
        if (gid < m) {
            float e = __ldg(b3 + s);
            #pragma unroll
            for (int q = 0; q < 8; q++) e += sm[EP + q * TM + gid];
            out[g_sorted[start + gid]] = e;
        }
        // next gather overwrites Ft only after this group's threads pass GBAR
    }
}

// ---------------- launch ----------------
extern "C" void kernel_launch(void* const* d_in, const int* in_sizes, int n_in,
                              void* d_out, int out_size)
{
    const float* feats   = (const float*)d_in[0];
    const void*  species = d_in[1];
    const float* W1 = (const float*)d_in[2];
    const float* b1 = (const float*)d_in[3];
    const float* W2 = (const float*)d_in[4];
    const float* b2 = (const float*)d_in[5];
    const float* W3 = (const float*)d_in[6];
    const float* b3 = (const float*)d_in[7];
    float* out = (float*)d_out;
    const int n = out_size;

    int dev = 0;
    cudaGetDevice(&dev);
    int nsm = 148;
    cudaDeviceGetAttribute(&nsm, cudaDevAttrMultiProcessorCount, dev);

    void* meta_addr = nullptr;
    cudaGetSymbolAddress(&meta_addr, g_meta);
    cudaMemsetAsync(meta_addr, 0, 8 * sizeof(int));

    hist_kernel<<<nsm, 256>>>(species, n);
    scatter_kernel<<<nsm, 256>>>(species, n);

    const size_t smem_bytes = SMEM_FLOATS * sizeof(float);
    cudaFuncSetAttribute(mlp_ldg_kernel,
                         cudaFuncAttributeMaxDynamicSharedMemorySize,
                         (int)smem_bytes);
    mlp_ldg_kernel<<<nsm, 256, smem_bytes>>>(feats, W1, b1, W2, b2, W3, b3, out);
}

// round 9
// speedup vs baseline: 1.6653x; 1.4116x over previous
#include <cuda_runtime.h>
#include <cstdint>

typedef unsigned long long ull;

#define NSPECIES 4
#define FDIM 128
#define HDIM 64
#define MAXN 2000000
#define TM 128
#define LDF 132
#define NGROUPS 4
#define NTHREADS 512

// ---------------- device scratch ----------------
__device__ int g_meta[8];     // [0..3] counts, [4..7] scatter cursors
__device__ int g_sorted[MAXN];

// ---------------- packed f32x2 helpers (validated) ----------------
__device__ __forceinline__ ull pk(float lo, float hi) {
    ull r;
    asm("mov.b64 %0, {%1, %2};" : "=l"(r)
        : "r"(__float_as_uint(lo)), "r"(__float_as_uint(hi)));
    return r;
}
__device__ __forceinline__ void upk(ull v, float& lo, float& hi) {
    unsigned a, b;
    asm("mov.b64 {%0, %1}, %2;" : "=r"(a), "=r"(b) : "l"(v));
    lo = __uint_as_float(a);
    hi = __uint_as_float(b);
}
__device__ __forceinline__ ull ffma2(ull a, ull b, ull c) {
    ull d;
    asm("fma.rn.f32x2 %0, %1, %2, %3;" : "=l"(d) : "l"(a), "l"(b), "l"(c));
    return d;
}
__device__ __forceinline__ float fast_tanh(float x) {
    // tanh(x) = 1 - 2/(exp(2x)+1); stable at +/-inf.
    float e = __expf(2.0f * x);
    return 1.0f - __fdividef(2.0f, e + 1.0f);
}

// ---------------- species dtype detect + counting sort (validated) -------
__device__ __forceinline__ int detect64(const void* sp, int n) {
    const long long* p = (const long long*)sp;
    int m = n / 2 < 128 ? n / 2 : 128;
    int ok = 1;
    #pragma unroll 1
    for (int i = 0; i < m; i++) { long long v = p[i]; if (v < 0 || v > 3) { ok = 0; break; } }
    return ok;
}
__device__ __forceinline__ int load_sp(const void* sp, int i, int is64) {
    return is64 ? (int)((const long long*)sp)[i] : ((const int*)sp)[i];
}
__global__ void hist_kernel(const void* __restrict__ sp, int n) {
    __shared__ int hs[NSPECIES];
    if (threadIdx.x < NSPECIES) hs[threadIdx.x] = 0;
    __syncthreads();
    const int is64 = detect64(sp, n);
    const int stride = gridDim.x * blockDim.x;
    for (int i = blockIdx.x * blockDim.x + threadIdx.x; i < n; i += stride)
        atomicAdd(&hs[load_sp(sp, i, is64)], 1);
    __syncthreads();
    if (threadIdx.x < NSPECIES) atomicAdd(&g_meta[threadIdx.x], hs[threadIdx.x]);
}
__global__ void scatter_kernel(const void* __restrict__ sp, int n) {
    const int is64 = detect64(sp, n);
    int offs[NSPECIES];
    { int a = 0;
      #pragma unroll
      for (int s = 0; s < NSPECIES; s++) { offs[s] = a; a += g_meta[s]; } }
    const int stride = gridDim.x * blockDim.x;
    const int lane = threadIdx.x & 31;
    for (int i = blockIdx.x * blockDim.x + threadIdx.x; i < n; i += stride) {
        int s = load_sp(sp, i, is64);
        unsigned act = __activemask();
        unsigned peers = __match_any_sync(act, s);
        int leader = __ffs(peers) - 1;
        int cnt = __popc(peers);
        int base = 0;
        if (lane == leader) base = atomicAdd(&g_meta[NSPECIES + s], cnt);
        base = __shfl_sync(peers, base, leader);
        g_sorted[offs[s] + base + __popc(peers & ((1u << lane) - 1u))] = i;
    }
}

// ---------------- SMEM float-offset layout ----------------
// Per-group 64-row buffer: holds a 64-k chunk of Ft, later Ht (64 rows).
#define FBSZ (64 * LDF)                       // 8448 floats
#define OFF_FB 0                              // 4 groups: 33792
#define OFF_W1 (OFF_FB + NGROUPS * FBSZ)      // 33792 : W1[k][j] 128x64
#define OFF_W2 (OFF_W1 + FDIM * HDIM)         // 41984 : W2[k][j] 64x64
#define OFF_B1 (OFF_W2 + HDIM * HDIM)         // 46080
#define OFF_B2 (OFF_B1 + HDIM)
#define OFF_W3 (OFF_B2 + HDIM)
#define OFF_B3 (OFF_W3 + HDIM)                // 46272 (+8 pad)
#define OFF_EP (OFF_B3 + 8)                   // Epart[4][8][128]
#define SMEM_FLOATS (OFF_EP + NGROUPS * 8 * TM)  // 50376 floats = 201504 B

extern __shared__ float sm[];

#define GBAR(id) asm volatile("bar.sync %0, 128;" :: "r"(id) : "memory")

__global__ void __launch_bounds__(NTHREADS, 1)
mlp16_kernel(const float* __restrict__ feats,
             const float* __restrict__ W1, const float* __restrict__ b1,
             const float* __restrict__ W2, const float* __restrict__ b2,
             const float* __restrict__ W3, const float* __restrict__ b3,
             float* __restrict__ out)
{
    const int tid = threadIdx.x;
    const int g   = tid >> 7;          // group 0..3 (independent tiles)
    const int gid = tid & 127;
    const int tx  = gid & 15;
    const int ty  = gid >> 4;
    const int mA  = tx * 4;            // atoms mA..mA+3 and 64+mA..64+mA+3
    const int n0  = ty * 8;
    const int FB  = OFF_FB + g * FBSZ;
    const int EP  = OFF_EP + g * 8 * TM;
    const int barid = 1 + g;

    // ---- species / tile / quad tables ----
    int beg[NSPECIES], cnt[NSPECIES], tiles[NSPECIES], qp[NSPECIES + 1];
    { int a = 0, q = 0;
      #pragma unroll
      for (int s = 0; s < NSPECIES; s++) {
          cnt[s] = g_meta[s];
          beg[s] = a; a += cnt[s];
          tiles[s] = (cnt[s] + TM - 1) / TM;
          qp[s] = q; q += (tiles[s] + NGROUPS - 1) / NGROUPS;   // quads per species
      }
      qp[NSPECIES] = q; }
    const int nquads = qp[NSPECIES];

    const int qpc = (nquads + gridDim.x - 1) / gridDim.x;
    const int q0 = blockIdx.x * qpc;
    const int q1 = min(q0 + qpc, nquads);

    int cur_s = -1;
    for (int q = q0; q < q1; q++) {
        int s = 3;
        if (q < qp[1]) s = 0; else if (q < qp[2]) s = 1; else if (q < qp[3]) s = 2;

        // ---- weight staging on species change (whole CTA, q is uniform) ----
        if (s != cur_s) {
            __syncthreads();           // all groups done with old weights
            for (int i = tid; i < FDIM * HDIM; i += NTHREADS)
                sm[OFF_W1 + i] = W1[s * FDIM * HDIM + i];
            for (int i = tid; i < HDIM * HDIM; i += NTHREADS)
                sm[OFF_W2 + i] = W2[s * HDIM * HDIM + i];
            if (tid < HDIM) {
                sm[OFF_B1 + tid] = b1[s * HDIM + tid];
                sm[OFF_B2 + tid] = b2[s * HDIM + tid];
                sm[OFF_W3 + tid] = W3[s * HDIM + tid];
            }
            if (tid == 0) sm[OFF_B3] = b3[s];
            cur_s = s;
            __syncthreads();
        }

        const int tile = (q - qp[s]) * NGROUPS + g;
        if (tile >= tiles[s]) continue;            // tail quad: group idles
        const int start = beg[s] + tile * TM;
        const int m = min(TM, cnt[s] - tile * TM);

        const int ridx = gid < m ? gid : m - 1;
        const int atom = g_sorted[start + ridx];
        const float4* src = (const float4*)(feats + (size_t)atom * FDIM);

        ull acc[8][4];
        {
            const ull* b1p = (const ull*)(sm + OFF_B1 + n0);
            const ull bi[4] = { b1p[0], b1p[1], b1p[2], b1p[3] };
            #pragma unroll
            for (int a = 0; a < 8; a++)
                #pragma unroll
                for (int np = 0; np < 4; np++) acc[a][np] = bi[np];
        }

        // ---- layer 1 in two 64-k chunks through the group buffer ----
        #pragma unroll 1
        for (int c = 0; c < 2; c++) {
            // gather chunk c: rows 0..63 of FB = k in [64c, 64c+64)
            #pragma unroll 4
            for (int qq = 0; qq < 16; qq++) {
                float4 v = src[c * 16 + qq];
                const int r = qq * 4;
                sm[FB + (r + 0) * LDF + gid] = v.x;
                sm[FB + (r + 1) * LDF + gid] = v.y;
                sm[FB + (r + 2) * LDF + gid] = v.z;
                sm[FB + (r + 3) * LDF + gid] = v.w;
            }
            GBAR(barid);

            const float* w1c = sm + OFF_W1 + c * 64 * HDIM;
            #pragma unroll 4
            for (int k = 0; k < 64; k++) {
                const float4 a0 = *(const float4*)(sm + FB + k * LDF + mA);
                const float4 a1 = *(const float4*)(sm + FB + k * LDF + 64 + mA);
                const ulonglong2 w01 = *(const ulonglong2*)(w1c + k * HDIM + n0);
                const ulonglong2 w23 = *(const ulonglong2*)(w1c + k * HDIM + n0 + 4);
                const ull f[8] = { pk(a0.x, a0.x), pk(a0.y, a0.y), pk(a0.z, a0.z), pk(a0.w, a0.w),
                                   pk(a1.x, a1.x), pk(a1.y, a1.y), pk(a1.z, a1.z), pk(a1.w, a1.w) };
                const ull w[4] = { w01.x, w01.y, w23.x, w23.y };
                #pragma unroll
                for (int a = 0; a < 8; a++)
                    #pragma unroll
                    for (int np = 0; np < 4; np++)
                        acc[a][np] = ffma2(f[a], w[np], acc[a][np]);
            }
            GBAR(barid);               // chunk reads done before next overwrite
        }

        // ---- tanh -> Ht[j][atom] into FB rows 0..63 ----
        #pragma unroll
        for (int np = 0; np < 4; np++) {
            float lo[8], hi[8];
            #pragma unroll
            for (int a = 0; a < 8; a++) {
                float x, y;
                upk(acc[a][np], x, y);
                lo[a] = fast_tanh(x);
                hi[a] = fast_tanh(y);
            }
            *(float4*)(sm + FB + (n0 + 2 * np) * LDF + mA)          = make_float4(lo[0], lo[1], lo[2], lo[3]);
            *(float4*)(sm + FB + (n0 + 2 * np) * LDF + 64 + mA)     = make_float4(lo[4], lo[5], lo[6], lo[7]);
            *(float4*)(sm + FB + (n0 + 2 * np + 1) * LDF + mA)      = make_float4(hi[0], hi[1], hi[2], hi[3]);
            *(float4*)(sm + FB + (n0 + 2 * np + 1) * LDF + 64 + mA) = make_float4(hi[4], hi[5], hi[6], hi[7]);
        }
        GBAR(barid);

        // ---- layer 2 ----
        {
            const ull* b2p = (const ull*)(sm + OFF_B2 + n0);
            const ull bi[4] = { b2p[0], b2p[1], b2p[2], b2p[3] };
            #pragma unroll
            for (int a = 0; a < 8; a++)
                #pragma unroll
                for (int np = 0; np < 4; np++) acc[a][np] = bi[np];

            #pragma unroll 4
            for (int k = 0; k < HDIM; k++) {
                const float4 a0 = *(const float4*)(sm + FB + k * LDF + mA);
                const float4 a1 = *(const float4*)(sm + FB + k * LDF + 64 + mA);
                const ulonglong2 w01 = *(const ulonglong2*)(sm + OFF_W2 + k * HDIM + n0);
                const ulonglong2 w23 = *(const ulonglong2*)(sm + OFF_W2 + k * HDIM + n0 + 4);
                const ull f[8] = { pk(a0.x, a0.x), pk(a0.y, a0.y), pk(a0.z, a0.z), pk(a0.w, a0.w),
                                   pk(a1.x, a1.x), pk(a1.y, a1.y), pk(a1.z, a1.z), pk(a1.w, a1.w) };
                const ull w[4] = { w01.x, w01.y, w23.x, w23.y };
                #pragma unroll
                for (int a = 0; a < 8; a++)
                    #pragma unroll
                    for (int np = 0; np < 4; np++)
                        acc[a][np] = ffma2(f[a], w[np], acc[a][np]);
            }
        }

        // ---- tanh, dot W3 slice, partial energies ----
        {
            const ull* w3p = (const ull*)(sm + OFF_W3 + n0);
            const ull w3r[4] = { w3p[0], w3p[1], w3p[2], w3p[3] };
            #pragma unroll
            for (int a = 0; a < 8; a++) {
                ull e2 = pk(0.0f, 0.0f);
                #pragma unroll
                for (int np = 0; np < 4; np++) {
                    float x, y;
                    upk(acc[a][np], x, y);
                    e2 = ffma2(pk(fast_tanh(x), fast_tanh(y)), w3r[np], e2);
                }
                float e0, e1;
                upk(e2, e0, e1);
                const int col = (a < 4) ? (mA + a) : (64 + mA + a - 4);
                sm[EP + ty * TM + col] = e0 + e1;
            }
        }
        GBAR(barid);

        // ---- reduce 8 partials per atom ----
        if (gid < m) {
            float e = sm[OFF_B3];
            #pragma unroll
            for (int p = 0; p < 8; p++) e += sm[EP + p * TM + gid];
            out[g_sorted[start + gid]] = e;
        }
        GBAR(barid);   // EP/FB safe to overwrite next iteration
    }
}

// ---------------- launch ----------------
extern "C" void kernel_launch(void* const* d_in, const int* in_sizes, int n_in,
                              void* d_out, int out_size)
{
    const float* feats   = (const float*)d_in[0];
    const void*  species = d_in[1];
    const float* W1 = (const float*)d_in[2];
    const float* b1 = (const float*)d_in[3];
    const float* W2 = (const float*)d_in[4];
    const float* b2 = (const float*)d_in[5];
    const float* W3 = (const float*)d_in[6];
    const float* b3 = (const float*)d_in[7];
    float* out = (float*)d_out;
    const int n = out_size;

    int dev = 0;
    cudaGetDevice(&dev);
    int nsm = 148;
    cudaDeviceGetAttribute(&nsm, cudaDevAttrMultiProcessorCount, dev);

    void* meta_addr = nullptr;
    cudaGetSymbolAddress(&meta_addr, g_meta);
    cudaMemsetAsync(meta_addr, 0, 8 * sizeof(int));

    hist_kernel<<<nsm, 256>>>(species, n);
    scatter_kernel<<<nsm, 256>>>(species, n);

    const size_t smem_bytes = SMEM_FLOATS * sizeof(float);
    cudaFuncSetAttribute(mlp16_kernel,
                         cudaFuncAttributeMaxDynamicSharedMemorySize,
                         (int)smem_bytes);
    mlp16_kernel<<<nsm, NTHREADS, smem_bytes>>>(feats, W1, b1, W2, b2, W3, b3, out);
}